// round 15
// baseline (speedup 1.0000x reference)
#include <cuda_runtime.h>
#include <math_constants.h>
#include <cstdint>
#include <cstddef>

// ---------------------------------------------------------------------------
// Problem constants
// ---------------------------------------------------------------------------
namespace cfg {
constexpr int Bb   = 4;
constexpr int Ls   = 2048;
constexpr int Din  = 512;
constexpr int Hh   = 8;
constexpr int Dh   = 64;
constexpr int Dmid = 2048;
constexpr int Mtok = Bb * Ls;   // 8192 tokens
}

// ---------------------------------------------------------------------------
// Scratch (static device globals — no allocations anywhere)
// ---------------------------------------------------------------------------
__device__ float g_Q[cfg::Bb * cfg::Hh * cfg::Ls * cfg::Dh];   // [b,h,l,d] tf32 bits
__device__ float g_K[cfg::Bb * cfg::Hh * cfg::Ls * cfg::Dh];   // tf32 bits
__device__ float g_V[cfg::Bb * cfg::Hh * cfg::Ls * cfg::Dh];   // tf32 bits
__device__ float g_attn[cfg::Mtok * cfg::Din];                 // tf32 bits
__device__ float g_proj[cfg::Mtok * cfg::Din];                 // fp32
__device__ float g_h1[cfg::Mtok * cfg::Din];                   // fp32 (residual)
__device__ float g_h1t[cfg::Mtok * cfg::Din];                  // tf32 bits (FFN1 A)
__device__ float g_mid[cfg::Mtok * cfg::Dmid];                 // tf32 bits
__device__ float g_ff[cfg::Mtok * cfg::Din];                   // fp32

// tf32 inputs; TRANSPOSED tf32 weights (Bt[n][k], K-major, for ldmatrix B)
__device__ float g_qt[cfg::Mtok * cfg::Din];
__device__ float g_kt[cfg::Mtok * cfg::Din];
__device__ float g_vt[cfg::Mtok * cfg::Din];
__device__ float g_WQt[cfg::Din * cfg::Din];
__device__ float g_WKt[cfg::Din * cfg::Din];
__device__ float g_WVt[cfg::Din * cfg::Din];
__device__ float g_WOt[cfg::Din * cfg::Din];
__device__ float g_W1t[cfg::Dmid * cfg::Din];   // [2048][512]
__device__ float g_W2t[cfg::Din * cfg::Dmid];   // [512][2048]

// ---------------------------------------------------------------------------
// PTX helpers
// ---------------------------------------------------------------------------
__device__ __forceinline__ void cpa16(void* smem, const void* gmem) {
    unsigned sa = (unsigned)__cvta_generic_to_shared(smem);
    asm volatile("cp.async.cg.shared.global [%0], [%1], 16;" :: "r"(sa), "l"(gmem));
}
__device__ __forceinline__ void cpa_commit() {
    asm volatile("cp.async.commit_group;");
}
template <int N>
__device__ __forceinline__ void cpa_wait() {
    asm volatile("cp.async.wait_group %0;" :: "n"(N));
}

__device__ __forceinline__ unsigned f2tf(float f) {
    unsigned u;
    asm("cvt.rna.tf32.f32 %0, %1;" : "=r"(u) : "f"(f));
    return u;
}
__device__ __forceinline__ float f2tf_f(float f) { return __uint_as_float(f2tf(f)); }

// mma.m16n8k8 tf32: A 4 regs, B 2 regs, C/D 4 floats (in-place accumulate)
__device__ __forceinline__ void mma_tf32_16n8k8(float d[4], const unsigned a[4],
                                                const unsigned b[2]) {
    asm volatile(
        "mma.sync.aligned.m16n8k8.row.col.f32.tf32.tf32.f32 "
        "{%0,%1,%2,%3}, {%4,%5,%6,%7}, {%8,%9}, {%0,%1,%2,%3};"
        : "+f"(d[0]), "+f"(d[1]), "+f"(d[2]), "+f"(d[3])
        : "r"(a[0]), "r"(a[1]), "r"(a[2]), "r"(a[3]), "r"(b[0]), "r"(b[1]));
}

// ldmatrix: lane L receives word (L%4) of row (L/4) of each 8x8 b16 matrix.
// For 32-bit tf32, each "word" is one element -> exactly the mma fragment map.
__device__ __forceinline__ void ldsm_x4(unsigned r[4], unsigned addr) {
    asm volatile("ldmatrix.sync.aligned.m8n8.x4.shared.b16 {%0,%1,%2,%3}, [%4];"
        : "=r"(r[0]), "=r"(r[1]), "=r"(r[2]), "=r"(r[3]) : "r"(addr));
}
__device__ __forceinline__ void ldsm_x2(unsigned r[2], unsigned addr) {
    asm volatile("ldmatrix.sync.aligned.m8n8.x2.shared.b16 {%0,%1}, [%2];"
        : "=r"(r[0]), "=r"(r[1]) : "r"(addr));
}

// ---------------------------------------------------------------------------
// Prologue: tf32 cvt for q/k/v; tiled transpose+cvt for weights.
// ---------------------------------------------------------------------------
struct Cvt3 { const float* s[3]; float* d[3]; int n[3]; };

__global__ __launch_bounds__(256) void cvt3_kernel(Cvt3 a)
{
    const int tid = blockIdx.x * 256 + threadIdx.x;
    const int stride = gridDim.x * 256;
#pragma unroll
    for (int seg = 0; seg < 3; seg++) {
        const float4* src = (const float4*)a.s[seg];
        float4*       dst = (float4*)a.d[seg];
        const int n4 = a.n[seg] >> 2;
        for (int i = tid; i < n4; i += stride) {
            float4 v = src[i];
            v.x = f2tf_f(v.x); v.y = f2tf_f(v.y);
            v.z = f2tf_f(v.z); v.w = f2tf_f(v.w);
            dst[i] = v;
        }
    }
}

// Wt[n][k] = tf32(W[k][n]).  block 32x8, grid (N/32, K/32).
__global__ __launch_bounds__(256) void transpose_cvt_kernel(
    const float* __restrict__ W, float* __restrict__ Wt, int K, int N)
{
    __shared__ float t[32][33];
    const int n0 = blockIdx.x * 32, k0 = blockIdx.y * 32;
    const int tx = threadIdx.x, ty = threadIdx.y;
#pragma unroll
    for (int i = 0; i < 32; i += 8)
        t[ty + i][tx] = f2tf_f(W[(size_t)(k0 + ty + i) * N + n0 + tx]);
    __syncthreads();
#pragma unroll
    for (int i = 0; i < 32; i += 8)
        Wt[(size_t)(n0 + ty + i) * K + k0 + tx] = t[tx][ty + i];
}

// ---------------------------------------------------------------------------
// Raw-mma tf32 GEMM with LDSM operand path.
// C[M,N] = A[M,K] * Bt[N,K]^T, fp32 accum, operands pre-truncated tf32 bits.
// Block tile 128x128x32, 256 threads (8 warps, 2x4), warp tile 64x32.
// A tile [128m][32k] stride 36; B tile [128n][32k] stride 36 (both %32==4:
// LDSM rows hit banks 4r..4r+3, covering all 32 banks once -> conflict-free).
// A-frag: 1 ldmatrix.x4;  B-frag: 1 ldmatrix.x2.  3-stage cp.async, 1
// barrier/iter, 2 CTAs/SM.
// Epilogues: 0 plain fp32, 2 head-split [b,h,l,64]+tf32, 3 relu+tf32.
// ---------------------------------------------------------------------------
constexpr int BM = 128, BN = 128, BK = 32;
constexpr int ALD = BK + 4;        // 36
constexpr int BLD = BK + 4;        // 36 (B tile is [n][k])
constexpr int AS_F = BM * ALD;     // 4608 floats / stage
constexpr int BS_F = BN * BLD;     // 4608 floats / stage
constexpr int GST  = 3;
constexpr size_t GEMM_SMEM = (size_t)GST * (AS_F + BS_F) * sizeof(float);  // 110,592 B

template <int EPI>
__device__ __forceinline__ void gemm_dev(
    const float* __restrict__ A, const float* __restrict__ Bt,
    float* __restrict__ C, int M, int N, int K)
{
    extern __shared__ float gsm[];
    float* As = gsm;
    float* Bs = gsm + GST * AS_F;

    const int tid  = threadIdx.x;
    const int bm   = blockIdx.y * BM;
    const int bn   = blockIdx.x * BN;
    const int warp = tid >> 5;
    const int lane = tid & 31;
    const int g    = lane >> 2;    // 0..7
    const int q    = lane & 3;     // 0..3
    const int wr   = warp >> 2;    // 0..1  (rows wr*64)
    const int wc   = warp & 3;     // 0..3  (cols wc*32)

    float acc[4][4][4];
#pragma unroll
    for (int mi = 0; mi < 4; mi++)
#pragma unroll
        for (int ni = 0; ni < 4; ni++)
#pragma unroll
            for (int e = 0; e < 4; e++) acc[mi][ni][e] = 0.0f;

    auto load_tiles = [&](int buf, int kt) {
        const int k0 = kt * BK;
        float* Ab = As + buf * AS_F;
        float* Bb = Bs + buf * BS_F;
        // A tile: 128 rows x 32 floats = 1024 float4, 4 per thread
#pragma unroll
        for (int i = 0; i < 4; i++) {
            int lin = tid + i * 256;          // 0..1023
            int r   = lin >> 3;               // 0..127
            int c4  = (lin & 7) * 4;          // 0..28
            cpa16(Ab + r * ALD + c4, A + (size_t)(bm + r) * K + k0 + c4);
        }
        // B tile: 128 n-rows x 32 k-floats (from Bt[n][k])
#pragma unroll
        for (int i = 0; i < 4; i++) {
            int lin = tid + i * 256;
            int r   = lin >> 3;
            int c4  = (lin & 7) * 4;
            cpa16(Bb + r * BLD + c4, Bt + (size_t)(bn + r) * K + k0 + c4);
        }
        cpa_commit();
    };

    const int nkt = K / BK;       // 16 or 64
    load_tiles(0, 0);
    load_tiles(1, 1);

    // Per-lane LDSM address offsets (bytes).
    const int lrow = lane & 7;            // row within 8x8 matrix
    const int lbit = (lane >> 3) & 1;     // matrix row-half (A) / matrix id (B)
    const int lco4 = (lane >> 4) * 4;     // A matrices 2,3: col +4
    const unsigned sA0 = (unsigned)__cvta_generic_to_shared(As);
    const unsigned sB0 = (unsigned)__cvta_generic_to_shared(Bs);
    const unsigned aoff = ((wr * 64 + lbit * 8 + lrow) * ALD + lco4) * 4;
    const unsigned boff = ((wc * 32 + lrow) * BLD + lbit * 4) * 4;

    for (int kt = 0; kt < nkt; kt++) {
        if (kt + 1 < nkt) cpa_wait<1>(); else cpa_wait<0>();
        __syncthreads();
        if (kt + 2 < nkt) load_tiles((kt + 2) % GST, kt + 2);

        const int buf = kt % GST;
        const unsigned abase = sA0 + buf * (AS_F * 4) + aoff;
        const unsigned bbase = sB0 + buf * (BS_F * 4) + boff;

#pragma unroll
        for (int j = 0; j < 4; j++) {             // k8 chunks within BK=32
            unsigned bfr[4][2];
#pragma unroll
            for (int ni = 0; ni < 4; ni++)
                ldsm_x2(bfr[ni], bbase + (unsigned)(ni * 8 * BLD * 4 + j * 32));
#pragma unroll
            for (int mi = 0; mi < 4; mi++) {
                unsigned a[4];
                ldsm_x4(a, abase + (unsigned)(mi * 16 * ALD * 4 + j * 32));
#pragma unroll
                for (int ni = 0; ni < 4; ni++)
                    mma_tf32_16n8k8(acc[mi][ni], a, bfr[ni]);
            }
        }
    }

    // ---- Epilogue: registers -> gmem directly ----
#pragma unroll
    for (int mi = 0; mi < 4; mi++) {
        const int gr0 = bm + wr * 64 + mi * 16 + g;
        const int gr1 = gr0 + 8;
#pragma unroll
        for (int ni = 0; ni < 4; ni++) {
            const int gc = bn + wc * 32 + ni * 8 + 2 * q;
            float d0 = acc[mi][ni][0], d1 = acc[mi][ni][1];
            float d2 = acc[mi][ni][2], d3 = acc[mi][ni][3];
            if (EPI == 3) {
                d0 = fmaxf(d0, 0.0f); d1 = fmaxf(d1, 0.0f);
                d2 = fmaxf(d2, 0.0f); d3 = fmaxf(d3, 0.0f);
            }
            if (EPI == 2) {
                int h = gc >> 6, d = gc & 63;
                int b0 = gr0 >> 11, l0i = gr0 & (cfg::Ls - 1);
                int b1 = gr1 >> 11, l1i = gr1 & (cfg::Ls - 1);
                float2 w0 = { f2tf_f(d0), f2tf_f(d1) };
                float2 w1 = { f2tf_f(d2), f2tf_f(d3) };
                *(float2*)&C[(((size_t)(b0 * cfg::Hh + h) * cfg::Ls + l0i) << 6) + d] = w0;
                *(float2*)&C[(((size_t)(b1 * cfg::Hh + h) * cfg::Ls + l1i) << 6) + d] = w1;
            } else if (EPI == 3) {
                float2 w0 = { f2tf_f(d0), f2tf_f(d1) };
                float2 w1 = { f2tf_f(d2), f2tf_f(d3) };
                *(float2*)&C[(size_t)gr0 * N + gc] = w0;
                *(float2*)&C[(size_t)gr1 * N + gc] = w1;
            } else {
                float2 w0 = { d0, d1 };
                float2 w1 = { d2, d3 };
                *(float2*)&C[(size_t)gr0 * N + gc] = w0;
                *(float2*)&C[(size_t)gr1 * N + gc] = w1;
            }
        }
    }
}

template <int EPI>
__global__ __launch_bounds__(256, 2) void gemm_tf32(
    const float* __restrict__ A, const float* __restrict__ Bt,
    float* __restrict__ C, int M, int N, int K)
{
    gemm_dev<EPI>(A, Bt, C, M, N, K);
}

// Fused QKV projection: blockIdx.z selects (input, weight, output) triple.
__global__ __launch_bounds__(256, 2) void gemm_qkv(
    const float* __restrict__ q, const float* __restrict__ k,
    const float* __restrict__ v,
    const float* __restrict__ WQ, const float* __restrict__ WK,
    const float* __restrict__ WV,
    float* __restrict__ Qd, float* __restrict__ Kd, float* __restrict__ Vd)
{
    const int z = blockIdx.z;
    const float* A = (z == 0) ? q : (z == 1) ? k : v;
    const float* W = (z == 0) ? WQ : (z == 1) ? WK : WV;
    float* C       = (z == 0) ? Qd : (z == 1) ? Kd : Vd;
    gemm_dev<2>(A, W, C, cfg::Mtok, cfg::Din, cfg::Din);
}

// ---------------------------------------------------------------------------
// Flash attention (unchanged: register-resident S/O, m16n8k8 tf32)
// ---------------------------------------------------------------------------
constexpr int FQ2  = 128;
constexpr int QSTR = 68;
constexpr int KSTR = 68;
constexpr int VSTR = 72;

constexpr int SM_Q = 0;
constexpr int SM_K = SM_Q + FQ2 * QSTR;
constexpr int SM_V = SM_K + 2 * 64 * KSTR;
constexpr int FLASH2_FLOATS = SM_V + 2 * 64 * VSTR;
constexpr size_t FLASH2_SMEM = (size_t)FLASH2_FLOATS * sizeof(float);  // 106,496 B

__global__ __launch_bounds__(256, 2) void flash2_kernel(
    const float* __restrict__ Qg, const float* __restrict__ Kg,
    const float* __restrict__ Vg, const float* __restrict__ maskg,
    float* __restrict__ Og)
{
    extern __shared__ float sm[];
    float* Qs = sm + SM_Q;
    float* Ks = sm + SM_K;
    float* Vs = sm + SM_V;

    const int tid  = threadIdx.x;
    const int warp = tid >> 5;
    const int lane = tid & 31;
    const int g    = lane >> 2;
    const int q    = lane & 3;
    const int b    = blockIdx.z;
    const int h    = blockIdx.y;
    const int q0   = blockIdx.x * FQ2;
    const int wrow = warp * 16;

    const size_t bh = (size_t)(b * cfg::Hh + h) * cfg::Ls;
    const float* Qbase = Qg + (bh + q0) * cfg::Dh;

#pragma unroll
    for (int i = 0; i < 8; i++) {
        int lin = tid + i * 256;
        int r = lin >> 4, c4 = (lin & 15) * 4;
        cpa16(&Qs[r * QSTR + c4], Qbase + r * cfg::Dh + c4);
    }

    auto loadKV = [&](int buf, int kt) {
        const float* Kb = Kg + (bh + kt * 64) * cfg::Dh;
        const float* Vb = Vg + (bh + kt * 64) * cfg::Dh;
#pragma unroll
        for (int i = 0; i < 4; i++) {
            int lin = tid + i * 256;
            int r = lin >> 4, c4 = (lin & 15) * 4;
            cpa16(&Ks[buf * 64 * KSTR + r * KSTR + c4], Kb + r * cfg::Dh + c4);
            cpa16(&Vs[buf * 64 * VSTR + r * VSTR + c4], Vb + r * cfg::Dh + c4);
        }
    };
    loadKV(0, 0);
    cpa_commit();

    float m0 = -CUDART_INF_F, m1 = -CUDART_INF_F;
    float l0 = 0.0f, l1 = 0.0f;
    float o[8][4];
#pragma unroll
    for (int t = 0; t < 8; t++)
#pragma unroll
        for (int e = 0; e < 4; e++) o[t][e] = 0.0f;

    const float* mrow0 = maskg + ((size_t)b * cfg::Ls + q0 + wrow + g) * cfg::Ls;
    const float* mrow1 = mrow0 + 8 * (size_t)cfg::Ls;

    const unsigned* Qu = (const unsigned*)Qs;
    const int srcA = (lane & 28) | (q >> 1);
    const int srcB = srcA + 2;
    const bool odd = (q & 1) != 0;

    for (int kt = 0; kt < cfg::Ls / 64; kt++) {
        const int cur = kt & 1;
        cpa_wait<0>();
        __syncthreads();
        if (kt + 1 < cfg::Ls / 64) { loadKV(cur ^ 1, kt + 1); cpa_commit(); }

        const unsigned* Ku = (const unsigned*)(Ks + cur * 64 * KSTR);
        const unsigned* Vu = (const unsigned*)(Vs + cur * 64 * VSTR);

        float s[8][4];
#pragma unroll
        for (int t = 0; t < 8; t++)
#pragma unroll
            for (int e = 0; e < 4; e++) s[t][e] = 0.0f;

#pragma unroll
        for (int j = 0; j < 8; j++) {
            unsigned a[4];
            a[0] = Qu[(wrow + g) * QSTR + j * 8 + q];
            a[1] = Qu[(wrow + g + 8) * QSTR + j * 8 + q];
            a[2] = Qu[(wrow + g) * QSTR + j * 8 + q + 4];
            a[3] = Qu[(wrow + g + 8) * QSTR + j * 8 + q + 4];
#pragma unroll
            for (int t = 0; t < 8; t++) {
                unsigned bf[2];
                bf[0] = Ku[(t * 8 + g) * KSTR + j * 8 + q];
                bf[1] = Ku[(t * 8 + g) * KSTR + j * 8 + q + 4];
                mma_tf32_16n8k8(s[t], a, bf);
            }
        }

        const int kcol = kt * 64;
#pragma unroll
        for (int t = 0; t < 8; t++) {
            float2 mk0 = *(const float2*)(mrow0 + kcol + t * 8 + 2 * q);
            float2 mk1 = *(const float2*)(mrow1 + kcol + t * 8 + 2 * q);
            s[t][0] = s[t][0] * 0.125f + mk0.x;
            s[t][1] = s[t][1] * 0.125f + mk0.y;
            s[t][2] = s[t][2] * 0.125f + mk1.x;
            s[t][3] = s[t][3] * 0.125f + mk1.y;
        }

        float mx0 = -CUDART_INF_F, mx1 = -CUDART_INF_F;
#pragma unroll
        for (int t = 0; t < 8; t++) {
            mx0 = fmaxf(mx0, fmaxf(s[t][0], s[t][1]));
            mx1 = fmaxf(mx1, fmaxf(s[t][2], s[t][3]));
        }
        mx0 = fmaxf(mx0, __shfl_xor_sync(0xffffffffu, mx0, 1));
        mx0 = fmaxf(mx0, __shfl_xor_sync(0xffffffffu, mx0, 2));
        mx1 = fmaxf(mx1, __shfl_xor_sync(0xffffffffu, mx1, 1));
        mx1 = fmaxf(mx1, __shfl_xor_sync(0xffffffffu, mx1, 2));

        const float m0n = fmaxf(m0, mx0);
        const float m1n = fmaxf(m1, mx1);
        const float c0  = __expf(m0 - m0n);
        const float c1  = __expf(m1 - m1n);

        float sum0 = 0.0f, sum1 = 0.0f;
#pragma unroll
        for (int t = 0; t < 8; t++) {
            s[t][0] = __expf(s[t][0] - m0n);
            s[t][1] = __expf(s[t][1] - m0n);
            s[t][2] = __expf(s[t][2] - m1n);
            s[t][3] = __expf(s[t][3] - m1n);
            sum0 += s[t][0] + s[t][1];
            sum1 += s[t][2] + s[t][3];
        }
        sum0 += __shfl_xor_sync(0xffffffffu, sum0, 1);
        sum0 += __shfl_xor_sync(0xffffffffu, sum0, 2);
        sum1 += __shfl_xor_sync(0xffffffffu, sum1, 1);
        sum1 += __shfl_xor_sync(0xffffffffu, sum1, 2);

        l0 = l0 * c0 + sum0;
        l1 = l1 * c1 + sum1;
        m0 = m0n;
        m1 = m1n;

#pragma unroll
        for (int t = 0; t < 8; t++) {
            o[t][0] *= c0; o[t][1] *= c0;
            o[t][2] *= c1; o[t][3] *= c1;
        }

#pragma unroll
        for (int j = 0; j < 8; j++) {
            float u0 = __shfl_sync(0xffffffffu, s[j][0], srcA);
            float u1 = __shfl_sync(0xffffffffu, s[j][1], srcA);
            float v0 = __shfl_sync(0xffffffffu, s[j][0], srcB);
            float v1 = __shfl_sync(0xffffffffu, s[j][1], srcB);
            float w0 = __shfl_sync(0xffffffffu, s[j][2], srcA);
            float w1 = __shfl_sync(0xffffffffu, s[j][3], srcA);
            float x0 = __shfl_sync(0xffffffffu, s[j][2], srcB);
            float x1 = __shfl_sync(0xffffffffu, s[j][3], srcB);
            unsigned a[4];
            a[0] = f2tf(odd ? u1 : u0);
            a[1] = f2tf(odd ? w1 : w0);
            a[2] = f2tf(odd ? v1 : v0);
            a[3] = f2tf(odd ? x1 : x0);
#pragma unroll
            for (int t = 0; t < 8; t++) {
                unsigned bf[2];
                bf[0] = Vu[(j * 8 + q) * VSTR + t * 8 + g];
                bf[1] = Vu[(j * 8 + q + 4) * VSTR + t * 8 + g];
                mma_tf32_16n8k8(o[t], a, bf);
            }
        }
    }

    const float inv0 = 1.0f / l0;
    const float inv1 = 1.0f / l1;
    float* orow0 = Og + ((size_t)b * cfg::Ls + q0 + wrow + g) * cfg::Din + h * cfg::Dh;
    float* orow1 = orow0 + 8 * (size_t)cfg::Din;
#pragma unroll
    for (int t = 0; t < 8; t++) {
        float2 w0 = { f2tf_f(o[t][0] * inv0), f2tf_f(o[t][1] * inv0) };
        float2 w1 = { f2tf_f(o[t][2] * inv1), f2tf_f(o[t][3] * inv1) };
        *(float2*)&orow0[t * 8 + 2 * q] = w0;
        *(float2*)&orow1[t * 8 + 2 * q] = w1;
    }
}

// ---------------------------------------------------------------------------
// Fused residual-add + LayerNorm over last dim (512). One block per row.
// ---------------------------------------------------------------------------
template <bool T32>
__global__ __launch_bounds__(128) void ln_add_kernel(
    const float* __restrict__ x, const float* __restrict__ y,
    float* __restrict__ out, float* __restrict__ out_t)
{
    const int row = blockIdx.x;
    const float* px = x + (size_t)row * cfg::Din;
    const float* py = y + (size_t)row * cfg::Din;

    float v[4];
    float s = 0.0f, sq = 0.0f;
#pragma unroll
    for (int i = 0; i < 4; i++) {
        int c = threadIdx.x + i * 128;
        v[i] = px[c] + py[c];
        s  += v[i];
        sq += v[i] * v[i];
    }
#pragma unroll
    for (int o = 16; o > 0; o >>= 1) {
        s  += __shfl_xor_sync(0xffffffffu, s, o);
        sq += __shfl_xor_sync(0xffffffffu, sq, o);
    }
    __shared__ float ws[4], wq[4];
    __shared__ float mean_s, inv_s;
    const int warp = threadIdx.x >> 5, lane = threadIdx.x & 31;
    if (lane == 0) { ws[warp] = s; wq[warp] = sq; }
    __syncthreads();
    if (threadIdx.x == 0) {
        float S = ws[0] + ws[1] + ws[2] + ws[3];
        float Q = wq[0] + wq[1] + wq[2] + wq[3];
        float mean = S * (1.0f / cfg::Din);
        float var  = Q * (1.0f / cfg::Din) - mean * mean;
        mean_s = mean;
        inv_s  = rsqrtf(var + 1e-5f);
    }
    __syncthreads();
    float* po = out + (size_t)row * cfg::Din;
    float* pt = out_t + (size_t)row * cfg::Din;
#pragma unroll
    for (int i = 0; i < 4; i++) {
        int c = threadIdx.x + i * 128;
        float r = (v[i] - mean_s) * inv_s;
        po[c] = r;
        if (T32) pt[c] = f2tf_f(r);
    }
}

// ---------------------------------------------------------------------------
// kernel_launch
// ---------------------------------------------------------------------------
extern "C" void kernel_launch(void* const* d_in, const int* in_sizes, int n_in,
                              void* d_out, int out_size)
{
    const float* query = (const float*)d_in[0];
    const float* key   = (const float*)d_in[1];
    const float* value = (const float*)d_in[2];
    const float* mask  = (const float*)d_in[3];
    const float* WQ    = (const float*)d_in[4];
    const float* WK    = (const float*)d_in[5];
    const float* WV    = (const float*)d_in[6];
    const float* WO    = (const float*)d_in[7];
    const float* W1    = (const float*)d_in[8];
    const float* W2    = (const float*)d_in[9];
    float* out = (float*)d_out;

    float *Qd, *Kd, *Vd, *attn, *proj, *h1, *h1t, *mid, *ff;
    float *qt, *kt, *vt, *WQt, *WKt, *WVt, *WOt, *W1t, *W2t;
    cudaGetSymbolAddress((void**)&Qd,   g_Q);
    cudaGetSymbolAddress((void**)&Kd,   g_K);
    cudaGetSymbolAddress((void**)&Vd,   g_V);
    cudaGetSymbolAddress((void**)&attn, g_attn);
    cudaGetSymbolAddress((void**)&proj, g_proj);
    cudaGetSymbolAddress((void**)&h1,   g_h1);
    cudaGetSymbolAddress((void**)&h1t,  g_h1t);
    cudaGetSymbolAddress((void**)&mid,  g_mid);
    cudaGetSymbolAddress((void**)&ff,   g_ff);
    cudaGetSymbolAddress((void**)&qt,   g_qt);
    cudaGetSymbolAddress((void**)&kt,   g_kt);
    cudaGetSymbolAddress((void**)&vt,   g_vt);
    cudaGetSymbolAddress((void**)&WQt,  g_WQt);
    cudaGetSymbolAddress((void**)&WKt,  g_WKt);
    cudaGetSymbolAddress((void**)&WVt,  g_WVt);
    cudaGetSymbolAddress((void**)&WOt,  g_WOt);
    cudaGetSymbolAddress((void**)&W1t,  g_W1t);
    cudaGetSymbolAddress((void**)&W2t,  g_W2t);

    cudaFuncSetAttribute(flash2_kernel, cudaFuncAttributeMaxDynamicSharedMemorySize,
                         (int)FLASH2_SMEM);
    cudaFuncSetAttribute(gemm_tf32<0>, cudaFuncAttributeMaxDynamicSharedMemorySize,
                         (int)GEMM_SMEM);
    cudaFuncSetAttribute(gemm_tf32<3>, cudaFuncAttributeMaxDynamicSharedMemorySize,
                         (int)GEMM_SMEM);
    cudaFuncSetAttribute(gemm_qkv, cudaFuncAttributeMaxDynamicSharedMemorySize,
                         (int)GEMM_SMEM);

    // -- prologue: tf32 cvt of q/k/v + transpose+cvt of all weights --
    const int nIn = cfg::Mtok * cfg::Din;
    Cvt3 cv;
    cv.s[0] = query; cv.d[0] = qt; cv.n[0] = nIn;
    cv.s[1] = key;   cv.d[1] = kt; cv.n[1] = nIn;
    cv.s[2] = value; cv.d[2] = vt; cv.n[2] = nIn;
    cvt3_kernel<<<1024, 256>>>(cv);

    dim3 tb(32, 8);
    transpose_cvt_kernel<<<dim3(16, 16), tb>>>(WQ, WQt, cfg::Din, cfg::Din);
    transpose_cvt_kernel<<<dim3(16, 16), tb>>>(WK, WKt, cfg::Din, cfg::Din);
    transpose_cvt_kernel<<<dim3(16, 16), tb>>>(WV, WVt, cfg::Din, cfg::Din);
    transpose_cvt_kernel<<<dim3(16, 16), tb>>>(WO, WOt, cfg::Din, cfg::Din);
    transpose_cvt_kernel<<<dim3(64, 16), tb>>>(W1, W1t, cfg::Din, cfg::Dmid);   // -> [2048][512]
    transpose_cvt_kernel<<<dim3(16, 64), tb>>>(W2, W2t, cfg::Dmid, cfg::Din);   // -> [512][2048]

    const dim3 gProj(cfg::Din / BN, cfg::Mtok / BM);        // (4, 64)
    const dim3 gQkv (cfg::Din / BN, cfg::Mtok / BM, 3);     // (4, 64, 3)
    const dim3 gFfn1(cfg::Dmid / BN, cfg::Mtok / BM);       // (16, 64)

    // Fused QKV projections (head-split + tf32 epilogue)
    gemm_qkv<<<gQkv, 256, GEMM_SMEM>>>(qt, kt, vt, WQt, WKt, WVt, Qd, Kd, Vd);

    // Flash attention (consumes tf32 Q/K/V, emits tf32 attn)
    dim3 gFlash(cfg::Ls / FQ2, cfg::Hh, cfg::Bb);           // (16, 8, 4)
    flash2_kernel<<<gFlash, 256, FLASH2_SMEM>>>(Qd, Kd, Vd, mask, attn);

    // Output projection + residual LN (fp32 out + tf32 copy for FFN1)
    gemm_tf32<0><<<gProj, 256, GEMM_SMEM>>>(attn, WOt, proj, cfg::Mtok, cfg::Din, cfg::Din);
    ln_add_kernel<true><<<cfg::Mtok, 128>>>(query, proj, h1, h1t);

    // FFN (FFN1: relu + tf32 epilogue; FFN2: fp32)
    gemm_tf32<3><<<gFfn1, 256, GEMM_SMEM>>>(h1t, W1t, mid, cfg::Mtok, cfg::Dmid, cfg::Din);
    gemm_tf32<0><<<gProj, 256, GEMM_SMEM>>>(mid, W2t, ff, cfg::Mtok, cfg::Din, cfg::Dmid);
    ln_add_kernel<false><<<cfg::Mtok, 128>>>(h1, ff, out, out);

    (void)in_sizes; (void)n_in; (void)out_size;
}